// round 1
// baseline (speedup 1.0000x reference)
#include <cuda_runtime.h>
#include <math.h>

#define BB 8
#define NN 2000
#define CC 81
#define NPAD 2048
#define METAS 93
#define MAXI 100
#define NTHREADS 1024

// -------- smem layout offsets (bytes) --------
#define OFF_OBOX    0                    // float4[2048]  = 32768
#define OFF_SCORE   32768                // float[2048]   = 8192  -> 40960
#define OFF_WARP    40960                // int[32]       = 128   -> 41088
#define OFF_STATS   41088                // int[4]        = 16    -> 41104
#define OFF_SIDX    41104                // ushort[2048]  = 4096  -> 45200
#define OFF_COMPACT 45200                // ushort[2048]  = 4096  -> 49296
#define OFF_OUT     49296                // ushort[128]   = 256   -> 49552
#define OFF_CLS     49552                // uchar[2048]   = 2048  -> 51600
#define OFF_KEEP    51600                // uchar[2048]   = 2048  -> 53648
#define OFF_CCLS    53648                // uchar[2048]   = 2048  -> 55696
#define SMEM_BYTES  55808

// Exact replication of the reference's box refine + clip (fp32, no FMA contraction).
__device__ __forceinline__ float4 refine_box(const float* __restrict__ rois,
                                             const float* __restrict__ bbox,
                                             int base, int cls,
                                             float wy1, float wx1, float wy2, float wx2) {
    float y1 = rois[base * 4 + 0];
    float x1 = rois[base * 4 + 1];
    float y2 = rois[base * 4 + 2];
    float x2 = rois[base * 4 + 3];
    const float* dp = bbox + ((size_t)base * CC + cls) * 4;
    float dy = __fmul_rn(dp[0], 0.1f);
    float dx = __fmul_rn(dp[1], 0.1f);
    float dh = __fmul_rn(dp[2], 0.2f);
    float dw = __fmul_rn(dp[3], 0.2f);
    float h = __fsub_rn(y2, y1);
    float w = __fsub_rn(x2, x1);
    float cy = __fadd_rn(__fadd_rn(y1, __fmul_rn(0.5f, h)), __fmul_rn(dy, h));
    float cx = __fadd_rn(__fadd_rn(x1, __fmul_rn(0.5f, w)), __fmul_rn(dx, w));
    float nh = __fmul_rn(h, expf(dh));
    float nw = __fmul_rn(w, expf(dw));
    float oy1 = __fsub_rn(cy, __fmul_rn(0.5f, nh));
    float ox1 = __fsub_rn(cx, __fmul_rn(0.5f, nw));
    float oy2 = __fadd_rn(cy, __fmul_rn(0.5f, nh));
    float ox2 = __fadd_rn(cx, __fmul_rn(0.5f, nw));
    oy1 = fminf(fmaxf(oy1, wy1), wy2);
    ox1 = fminf(fmaxf(ox1, wx1), wx2);
    oy2 = fminf(fmaxf(oy2, wy1), wy2);
    ox2 = fminf(fmaxf(ox2, wx1), wx2);
    return make_float4(oy1, ox1, oy2, ox2);
}

// Block-wide exclusive scan over per-thread pair counts (1024 threads = 32 warps).
// Returns exclusive prefix for this thread's pair; *total gets grand total.
__device__ __forceinline__ int scan_pairs(int cnt, int tid, int* s_warp, int* total) {
    int lane = tid & 31, warp = tid >> 5;
    int inc = cnt;
#pragma unroll
    for (int d = 1; d < 32; d <<= 1) {
        int v = __shfl_up_sync(0xffffffffu, inc, d);
        if (lane >= d) inc += v;
    }
    if (lane == 31) s_warp[warp] = inc;
    __syncthreads();
    if (warp == 0) {
        int v = s_warp[lane];
#pragma unroll
        for (int d = 1; d < 32; d <<= 1) {
            int u = __shfl_up_sync(0xffffffffu, v, d);
            if (lane >= d) v += u;
        }
        s_warp[lane] = v;
    }
    __syncthreads();
    *total = s_warp[31];
    int we = (warp == 0) ? 0 : s_warp[warp - 1];
    return we + inc - cnt;
}

extern "C" __global__ void __launch_bounds__(NTHREADS, 1)
detection_kernel(const float* __restrict__ rois,
                 const float* __restrict__ probs,
                 const float* __restrict__ bbox,
                 const float* __restrict__ meta,
                 float* __restrict__ out) {
    extern __shared__ unsigned char dsm[];
    float4* s_obox = (float4*)(dsm + OFF_OBOX);
    float* s_score = (float*)(dsm + OFF_SCORE);
    int* s_warp = (int*)(dsm + OFF_WARP);
    int* s_stats = (int*)(dsm + OFF_STATS);
    unsigned short* s_sidx = (unsigned short*)(dsm + OFF_SIDX);
    unsigned short* s_compact = (unsigned short*)(dsm + OFF_COMPACT);
    unsigned short* s_out = (unsigned short*)(dsm + OFF_OUT);
    unsigned char* s_cls = (unsigned char*)(dsm + OFF_CLS);
    unsigned char* s_keep = (unsigned char*)(dsm + OFF_KEEP);
    unsigned char* s_ccls = (unsigned char*)(dsm + OFF_CCLS);

    const int tid = threadIdx.x;
    const int b = blockIdx.x;

    // window per batch (scale uses image_meta row 0, window uses row b)
    float ih = meta[4];
    float iw = meta[5];
    float sy = __fsub_rn(ih, 1.0f);
    float sx = __fsub_rn(iw, 1.0f);
    const float* mb = meta + (size_t)b * METAS;
    float wy1 = __fsub_rn(mb[7], 0.0f) / sy;
    float wx1 = __fsub_rn(mb[8], 0.0f) / sx;
    float wy2 = __fsub_rn(mb[9], 1.0f) / sy;
    float wx2 = __fsub_rn(mb[10], 1.0f) / sx;

    // ---------- Phase A: per-ROI argmax, refine, offset box ----------
    for (int n = tid; n < NPAD; n += NTHREADS) {
        if (n < NN) {
            int base = b * NN + n;
            const float* pr = probs + (size_t)base * CC;
            float best = pr[0];
            int cls = 0;
#pragma unroll 4
            for (int c = 1; c < CC; c++) {
                float p = pr[c];
                if (p > best) { best = p; cls = c; }
            }
            float score = best;
            bool valid = (cls > 0) && (score >= 0.7f);
            float4 rb = refine_box(rois, bbox, base, cls, wy1, wx1, wy2, wx2);
            float off = __fmul_rn(4.0f, (float)cls);
            float4 ob;
            ob.x = __fadd_rn(rb.x, off);
            ob.y = __fadd_rn(rb.y, off);
            ob.z = __fadd_rn(rb.z, off);
            ob.w = __fadd_rn(rb.w, off);
            s_obox[n] = ob;
            s_cls[n] = (unsigned char)cls;
            s_score[n] = valid ? score : -1.0f;
        } else {
            s_score[n] = -2.0f;     // pad sorts to the very end
            s_cls[n] = 0;
            s_obox[n] = make_float4(0.f, 0.f, 0.f, 0.f);
        }
        s_sidx[n] = (unsigned short)n;
    }
    __syncthreads();

    // ---------- Phase B: bitonic sort of (score desc, idx asc), n=2048 ----------
    for (int k = 2; k <= NPAD; k <<= 1) {
        for (int j = k >> 1; j > 0; j >>= 1) {
            int t = tid;  // exactly 1024 pairs
            int i = ((t & ~(j - 1)) << 1) | (t & (j - 1));
            int p = i | j;
            bool up = ((i & k) == 0);
            float si = s_score[i], sp = s_score[p];
            unsigned short ii = s_sidx[i], ip = s_sidx[p];
            // "less" == comes first in final order: higher score, then lower idx
            bool less_ip = (si > sp) || (si == sp && ii < ip);
            bool doswap = up ? (!less_ip) : less_ip;
            if (doswap) {
                s_score[i] = sp; s_score[p] = si;
                s_sidx[i] = ip;  s_sidx[p] = ii;
            }
            __syncthreads();
        }
    }

    // ---------- Phase C: find M = count of valid (score > 0), sorted prefix ----------
    if (tid == 0) s_stats[0] = 0;
    __syncthreads();
    for (int n = tid; n < NPAD; n += NTHREADS) {
        bool v = s_score[n] > 0.0f;
        bool vn = (n + 1 < NPAD) ? (s_score[n + 1] > 0.0f) : false;
        if (v && !vn) s_stats[0] = n + 1;
    }
    __syncthreads();
    const int M = s_stats[0];

    // ---------- Phase D: greedy NMS (exact reference semantics) ----------
    for (int n = tid; n < NPAD; n += NTHREADS) s_keep[n] = (n < M) ? 1 : 0;
    __syncthreads();

    volatile unsigned char* v_keep = (volatile unsigned char*)s_keep;
    for (int i = 0; i < M; i++) {
        if (v_keep[i]) {
            float4 bi = s_obox[s_sidx[i]];
            float ai = __fmul_rn(__fsub_rn(bi.z, bi.x), __fsub_rn(bi.w, bi.y));
            for (int j = i + 1 + tid; j < M; j += NTHREADS) {
                if (v_keep[j]) {
                    float4 bj = s_obox[s_sidx[j]];
                    float iy = fmaxf(0.0f, __fsub_rn(fminf(bi.z, bj.z), fmaxf(bi.x, bj.x)));
                    float ix = fmaxf(0.0f, __fsub_rn(fminf(bi.w, bj.w), fmaxf(bi.y, bj.y)));
                    float inter = __fmul_rn(iy, ix);
                    float aj = __fmul_rn(__fsub_rn(bj.z, bj.x), __fsub_rn(bj.w, bj.y));
                    float den = __fadd_rn(__fsub_rn(__fadd_rn(ai, aj), inter), 1e-12f);
                    float iou = inter / den;
                    if (iou > 0.3f) v_keep[j] = 0;
                }
            }
            __syncthreads();
        }
    }

    // ---------- Phase E: compact kept entries (sorted order preserved) ----------
    int e0 = s_keep[2 * tid];
    int e1 = s_keep[2 * tid + 1];
    int m_total;
    int pos = scan_pairs(e0 + e1, tid, s_warp, &m_total);
    if (e0) {
        int p = 2 * tid;
        s_compact[pos] = (unsigned short)p;
        s_ccls[pos] = s_cls[s_sidx[p]];
    }
    if (e1) {
        int p = 2 * tid + 1;
        s_compact[pos + e0] = (unsigned short)p;
        s_ccls[pos + e0] = s_cls[s_sidx[p]];
    }
    __syncthreads();
    const int m = m_total;

    // ---------- Phase F: per-class rank cap (rank < MAXI) ----------
    for (int k = tid; k < NPAD; k += NTHREADS) {
        if (k < m) {
            unsigned char ck = s_ccls[k];
            int r = 0;
            for (int l = 0; l < k; l++) r += (s_ccls[l] == ck) ? 1 : 0;
            s_keep[k] = (r < MAXI) ? 1 : 0;   // reuse s_keep as "eligible"
        } else {
            s_keep[k] = 0;
        }
    }
    __syncthreads();

    // ---------- Phase G: select first 100 eligible (== top_k of masked scores) ----------
    int g0 = s_keep[2 * tid];
    int g1 = s_keep[2 * tid + 1];
    int elig_total;
    int opos = scan_pairs(g0 + g1, tid, s_warp, &elig_total);
    if (g0 && opos < MAXI) s_out[opos] = s_compact[2 * tid];
    if (g1 && (opos + g0) < MAXI) s_out[opos + g0] = s_compact[2 * tid + 1];
    __syncthreads();
    const int outCount = (elig_total < MAXI) ? elig_total : MAXI;

    // ---------- Phase H: write output ----------
    for (int r = tid; r < MAXI; r += NTHREADS) {
        float v0 = 0.f, v1 = 0.f, v2 = 0.f, v3 = 0.f, v4 = 0.f, v5 = 0.f;
        if (r < outCount) {
            int p = s_out[r];
            int orig = s_sidx[p];
            int cls = s_cls[orig];
            float sc = s_score[p];
            float4 rb = refine_box(rois, bbox, b * NN + orig, cls, wy1, wx1, wy2, wx2);
            v0 = rb.x; v1 = rb.y; v2 = rb.z; v3 = rb.w;
            v4 = (float)cls; v5 = sc;
        }
        float* o = out + ((size_t)b * MAXI + r) * 6;
        o[0] = v0; o[1] = v1; o[2] = v2; o[3] = v3; o[4] = v4; o[5] = v5;
    }
}

extern "C" void kernel_launch(void* const* d_in, const int* in_sizes, int n_in,
                              void* d_out, int out_size) {
    const float* rois  = (const float*)d_in[0];
    const float* probs = (const float*)d_in[1];
    const float* bbox  = (const float*)d_in[2];
    const float* meta  = (const float*)d_in[3];
    float* out = (float*)d_out;

    cudaFuncSetAttribute(detection_kernel,
                         cudaFuncAttributeMaxDynamicSharedMemorySize, SMEM_BYTES);
    detection_kernel<<<BB, NTHREADS, SMEM_BYTES>>>(rois, probs, bbox, meta, out);
}